// round 16
// baseline (speedup 1.0000x reference)
#include <cuda_runtime.h>
#include <cuda_bf16.h>
#include <cstdint>

// ParallelLinear: out[b,t,o] = sum_i x[b,t,i] * W[t,o,i] + bias[t,o]
// B=512, T=1024, ISIZE=OSIZE=64, fp32.
// R15: two kernels.
//  prep_w: split W into bf16 hi/lo directly in mma.m16n8k16 B-FRAGMENT order
//          (byte-identical to what R7's staged-smem + ldmatrix produced).
//  main:   R7 mainloop with ldmatrix replaced by coalesced LDG.128 fragment
//          loads; W prologue, smem and __syncthreads fully removed.

#define TT    1024
#define BB    512
#define KK    64
#define OO    64
#define BLOCK 128
#define ROWS  128

typedef unsigned int u32;

// W fragments: [t][ks][np] -> 1KB block: 32 x uint4 hi, then 32 x uint4 lo
static __device__ uint4 WSfrag[1024 * 4 * 4 * 64];   // 16 MB

// split fp32 pair -> packed bf16x2 hi and lo
__device__ __forceinline__ void split2(float ax, float ay, u32 &hi, u32 &lo) {
    float2 v = { ax, ay };
    __nv_bfloat162 hp = __float22bfloat162_rn(v);
    u32 h = *(u32*)&hp;
    float hx = __uint_as_float(h << 16);
    float hy = __uint_as_float(h & 0xFFFF0000u);
    float2 r = { v.x - hx, v.y - hy };
    __nv_bfloat162 lp = __float22bfloat162_rn(r);
    hi = h;
    lo = *(u32*)&lp;
}

__device__ __forceinline__ void mma_bf16(float* d, const u32* a, u32 b0, u32 b1) {
    asm volatile(
        "mma.sync.aligned.m16n8k16.row.col.f32.bf16.bf16.f32 "
        "{%0,%1,%2,%3}, {%4,%5,%6,%7}, {%8,%9}, {%0,%1,%2,%3};"
        : "+f"(d[0]), "+f"(d[1]), "+f"(d[2]), "+f"(d[3])
        : "r"(a[0]), "r"(a[1]), "r"(a[2]), "r"(a[3]), "r"(b0), "r"(b1));
}

// ---- prep kernel: one CTA per t ----
// Fragment u32 (lane l, reg j) of (ks, np) = u32 #(l&3) of the 16B at
// logical staged position (n_a = np*16 + (l>>2) + (j>>1)*8, chunk = 2ks+(j&1)),
// which maps back through the inverse n-perm / k-perm to W[t][o][2ip..2ip+1].
__global__ __launch_bounds__(128, 8)
void prep_w_kernel(const float* __restrict__ W)
{
    const int t   = blockIdx.x;
    const int tid = threadIdx.x;
    const int l   = tid & 31;
    const int np  = tid >> 5;          // warp = np

    const float* Wt = W + (size_t)t * (OO * KK);

    #pragma unroll
    for (int ks = 0; ks < 4; ks++) {
        u32 hv[4], lv[4];
        #pragma unroll
        for (int j = 0; j < 4; j++) {
            int n_a = np * 16 + (l >> 2) + ((j >> 1) << 3);
            int ch  = 2 * ks + (j & 1);
            int ipp = ch * 4 + (l & 3);                 // staged pair index 0..31
            int w8  = ipp & 7;                          // inverse k-perm within 8
            int ip  = (ipp & ~7) | (((w8 & 3) << 1) | (w8 >> 2));
            int m  = n_a >> 4, bb = (n_a >> 3) & 1;     // inverse n-perm
            int qq = (n_a >> 1) & 3, j2 = n_a & 1;
            int o  = (m << 4) | (qq << 2) | (bb << 1) | j2;
            float2 v = *(const float2*)(Wt + o * KK + 2 * ip);
            split2(v.x, v.y, hv[j], lv[j]);
        }
        uint4* dst = WSfrag + (((size_t)t * 4 + ks) * 4 + np) * 64;
        dst[l]      = make_uint4(hv[0], hv[1], hv[2], hv[3]);
        dst[32 + l] = make_uint4(lv[0], lv[1], lv[2], lv[3]);
    }
}

// ---- main kernel: R7 mainloop, no smem, no barriers ----
__global__ __launch_bounds__(BLOCK, 4)
void ParallelLinear_59133109732019_kernel(
    const float* __restrict__ x,     // [B, T, 64]
    const float* __restrict__ bias,  // [T, 64]
    float* __restrict__ out)         // [B, T, 64]
{
    const int t       = blockIdx.y;
    const int rowBase = blockIdx.x * ROWS;
    const int tid     = threadIdx.x;
    const int wid     = tid >> 5;
    const int lane    = tid & 31;
    const int g       = lane >> 2;       // row within 8-group
    const int q       = lane & 3;        // fragment column selector

    // x fragment base: rows (rowBase + wid*32 + mt*16 + g [+8]), col 4q (k-permuted)
    const size_t xrstride = (size_t)TT * KK;
    const float* xbase[2];
    #pragma unroll
    for (int mt = 0; mt < 2; mt++)
        xbase[mt] = x + (size_t)(rowBase + wid * 32 + mt * 16 + g) * xrstride
                      + (size_t)t * KK + 4 * q;

    // ---- prefetch ks=0 x data ----
    float4 xf[2][2];
    #pragma unroll
    for (int mt = 0; mt < 2; mt++) {
        xf[mt][0] = *(const float4*)(xbase[mt]);                  // row g
        xf[mt][1] = *(const float4*)(xbase[mt] + 8 * xrstride);   // row g+8
    }

    // ---- accumulators: 2 m-tiles x 8 n-tiles x 4 fp32 ----
    float d[2][8][4];
    #pragma unroll
    for (int mt = 0; mt < 2; mt++)
        #pragma unroll
        for (int nt = 0; nt < 8; nt++)
            #pragma unroll
            for (int e = 0; e < 4; e++) d[mt][nt][e] = 0.0f;

    const uint4* wtb = WSfrag + (size_t)t * 4 * 4 * 64;

    #pragma unroll
    for (int ks = 0; ks < 4; ks++) {
        // prefetch next k-step's x
        float4 xn[2][2];
        if (ks < 3) {
            #pragma unroll
            for (int mt = 0; mt < 2; mt++) {
                const float* bp = xbase[mt] + (ks + 1) * 16;
                xn[mt][0] = *(const float4*)(bp);
                xn[mt][1] = *(const float4*)(bp + 8 * xrstride);
            }
        }

        // build bf16 hi/lo A fragments (k-permuted: float4 -> R0/R2, R1/R3)
        u32 ah[2][4], al[2][4];
        #pragma unroll
        for (int mt = 0; mt < 2; mt++) {
            split2(xf[mt][0].x, xf[mt][0].y, ah[mt][0], al[mt][0]);   // row g,   k-low
            split2(xf[mt][1].x, xf[mt][1].y, ah[mt][1], al[mt][1]);   // row g+8, k-low
            split2(xf[mt][0].z, xf[mt][0].w, ah[mt][2], al[mt][2]);   // row g,   k-high
            split2(xf[mt][1].z, xf[mt][1].w, ah[mt][3], al[mt][3]);   // row g+8, k-high
        }

        #pragma unroll
        for (int np = 0; np < 4; np++) {
            const uint4* wb = wtb + ((size_t)ks * 4 + np) * 64;
            uint4 bh = wb[lane];          // coalesced LDG.128, L1/L2-hot
            uint4 bl = wb[32 + lane];

            #pragma unroll
            for (int mt = 0; mt < 2; mt++) {
                mma_bf16(d[mt][2 * np],     ah[mt], bh.x, bh.y);   // hi*hi
                mma_bf16(d[mt][2 * np + 1], ah[mt], bh.z, bh.w);
                mma_bf16(d[mt][2 * np],     ah[mt], bl.x, bl.y);   // hi*lo
                mma_bf16(d[mt][2 * np + 1], ah[mt], bl.z, bl.w);
                mma_bf16(d[mt][2 * np],     al[mt], bh.x, bh.y);   // lo*hi
                mma_bf16(d[mt][2 * np + 1], al[mt], bh.z, bh.w);
            }
        }

        #pragma unroll
        for (int mt = 0; mt < 2; mt++) {
            xf[mt][0] = xn[mt][0];
            xf[mt][1] = xn[mt][1];
        }
    }

    // ---- epilogue: bias via direct (L2-hot) loads, STG.128 stores ----
    const float* bt = bias + (size_t)t * OO;
    #pragma unroll
    for (int mt = 0; mt < 2; mt++) {
        int r0 = rowBase + wid * 32 + mt * 16 + g;
        float* o0 = out + (size_t)r0 * (TT * OO) + (size_t)t * OO;
        float* o1 = o0 + (size_t)8 * (TT * OO);
        #pragma unroll
        for (int m = 0; m < 4; m++) {
            int c = 16 * m + 4 * q;        // true cols c..c+3
            float4 bv = *(const float4*)(bt + c);
            float4 v0 = { d[mt][2 * m][0] + bv.x, d[mt][2 * m][1] + bv.y,
                          d[mt][2 * m + 1][0] + bv.z, d[mt][2 * m + 1][1] + bv.w };
            float4 v1 = { d[mt][2 * m][2] + bv.x, d[mt][2 * m][3] + bv.y,
                          d[mt][2 * m + 1][2] + bv.z, d[mt][2 * m + 1][3] + bv.w };
            *(float4*)(o0 + c) = v0;       // row r0
            *(float4*)(o1 + c) = v1;       // row r0 + 8
        }
    }
}

extern "C" void kernel_launch(void* const* d_in, const int* in_sizes, int n_in,
                              void* d_out, int out_size)
{
    const float* x    = (const float*)d_in[0];   // 512*1024*64 fp32
    const float* W    = (const float*)d_in[1];   // 1024*64*64 fp32
    const float* bias = (const float*)d_in[2];   // 1024*64 fp32
    float* out        = (float*)d_out;           // 512*1024*64 fp32

    prep_w_kernel<<<TT, 128>>>(W);

    dim3 grid(BB / ROWS, TT);   // (4, 1024)
    ParallelLinear_59133109732019_kernel<<<grid, BLOCK>>>(x, bias, out);
}